// round 11
// baseline (speedup 1.0000x reference)
#include <cuda_runtime.h>
#include <math.h>
#include <cstdint>

#define BB   4
#define RR   64
#define CC   192
#define WNN  16
#define WSZ  16
#define TAPS 9

// ---------------- device scratch ----------------
__device__ float g_t[BB * WNN];
__device__ float g_WeffB[BB * TAPS * 6 * 6144];        // B in mma-fragment order
__device__ float g_xA[(size_t)BB * 3 * RR * 6 * 2048]; // A frag-order, 3 dx shifts
__device__ float g_k1T[TAPS * WNN * CC];               // k1 transposed [tap][s][c]

__device__ __forceinline__ uint32_t f2tf(float f) {
    uint32_t u; asm("cvt.rna.tf32.f32 %0, %1;" : "=r"(u) : "f"(f)); return u;
}
__device__ __forceinline__ void mma_tf32(float* d, const uint32_t* a, const uint32_t* b) {
    asm volatile(
        "mma.sync.aligned.m16n8k8.row.col.f32.tf32.tf32.f32 "
        "{%0,%1,%2,%3}, {%4,%5,%6,%7}, {%8,%9}, {%0,%1,%2,%3};"
        : "+f"(d[0]), "+f"(d[1]), "+f"(d[2]), "+f"(d[3])
        : "r"(a[0]), "r"(a[1]), "r"(a[2]), "r"(a[3]), "r"(b[0]), "r"(b[1]));
}

// ---------------------------------------------------------------------------
// Kernel X: build A operand in mma-fragment order, tf32-rounded (validated)
// ---------------------------------------------------------------------------
__global__ void __launch_bounds__(256)
kX(const float* __restrict__ x) {
    int sy  = blockIdx.x;
    int dxi = blockIdx.y;
    int b   = blockIdx.z;
    int wid  = threadIdx.x >> 5;
    int lane = threadIdx.x & 31;

    int px = lane >> 1;
    int kk = (lane & 1) * 4;

    const float* xr = x + ((size_t)(b * RR + sy) * RR) * CC;

#pragma unroll 1
    for (int u = wid; u < 96; u += 8) {
        int cg = u >> 4;
        int ks = (u >> 2) & 3;
        int mi = u & 3;
        int sx = mi * 16 + px + dxi - 1;

        float4 v = make_float4(0.f, 0.f, 0.f, 0.f);
        if ((unsigned)sx < RR)
            v = *(const float4*)(xr + (size_t)sx * CC + cg * 32 + ks * 8 + kk);

        float* dst = g_xA + ((((size_t)b * 3 + dxi) * RR + sy) * 6 + cg) * 2048
                         + (ks * 4 + mi) * 128;
        int rbase = (kk >> 2) * 2 + (px >> 3);
        uint32_t vv[4] = { f2tf(v.x), f2tf(v.y), f2tf(v.z), f2tf(v.w) };
#pragma unroll
        for (int i = 0; i < 4; i++)
            dst[((px & 7) * 4 + i) * 4 + rbase] = __uint_as_float(vv[i]);
    }
}

// ---------------------------------------------------------------------------
// Kernel T: transpose conv1_w for coalesced kW reads (validated)
// ---------------------------------------------------------------------------
__global__ void kT(const float* __restrict__ k1) {
    int i = blockIdx.x * 256 + threadIdx.x;
    if (i >= TAPS * WNN * CC) return;
    int tap = i / (WNN * CC);
    int rc  = i - tap * (WNN * CC);
    g_k1T[i] = k1[(size_t)rc * TAPS + tap];
}

// ---------------------------------------------------------------------------
// Kernel A: pooled depthwise stats -> downchannel logits (validated)
// ---------------------------------------------------------------------------
__global__ void kA(const float* __restrict__ x, const float* __restrict__ k1,
                   const float* __restrict__ dcw, const float* __restrict__ dcb) {
    int b   = blockIdx.x >> 4;
    int win = blockIdx.x & 15;
    int c   = threadIdx.x;
    int rb  = win >> 2, cb = win & 3;
    const float* xp = x + ((size_t)b * RR * RR) * CC + c;
    int base = (rb * WSZ) * RR + cb * WSZ;

    float T = 0.f, r0 = 0.f, r15 = 0.f, c0 = 0.f, c15 = 0.f;
    float e00 = 0.f, e0f = 0.f, ef0 = 0.f, eff = 0.f;
    for (int i = 0; i < 16; i++) {
        float rowacc = 0.f, vj0 = 0.f, vj15 = 0.f;
#pragma unroll
        for (int j = 0; j < 16; j++) {
            float v = xp[(size_t)(base + i * RR + j) * CC];
            rowacc += v;
            if (j == 0)  { c0  += v; vj0  = v; }
            if (j == 15) { c15 += v; vj15 = v; }
        }
        T += rowacc;
        if (i == 0)  { r0  = rowacc; e00 = vj0; e0f = vj15; }
        if (i == 15) { r15 = rowacc; ef0 = vj0; eff = vj15; }
    }

    float Rex[3] = { r15, 0.f, r0 };
    float Cex[3] = { c15, 0.f, c0 };
    const float* kp = k1 + (size_t)(win * CC + c) * TAPS;
    float pooled = 0.f;
#pragma unroll
    for (int p = 0; p < 3; p++) {
#pragma unroll
        for (int q = 0; q < 3; q++) {
            float corner = 0.f;
            if (p == 0 && q == 0) corner = eff;
            if (p == 0 && q == 2) corner = ef0;
            if (p == 2 && q == 0) corner = e0f;
            if (p == 2 && q == 2) corner = e00;
            float S = T - Rex[p] - Cex[q] + corner;
            pooled += kp[p * 3 + q] * S;
        }
    }
    pooled *= (1.f / 256.f);
    float contrib = pooled * dcw[win * CC + c];

    __shared__ float red[192];
    red[c] = contrib;
    __syncthreads();
    for (int s = 96; s >= 6; s >>= 1) {
        if (c < s) red[c] += red[c + s];
        __syncthreads();
    }
    if (c == 0) {
        float tot = red[0] + red[1] + red[2] + red[3] + red[4] + red[5];
        g_t[b * WNN + win] = tot + dcb[win];
    }
}

// ---------------------------------------------------------------------------
// Kernel W: fused MLP (per-block recompute) + Weff in mma B-fragment order.
// ---------------------------------------------------------------------------
__global__ void __launch_bounds__(192)
kW(const float* __restrict__ gkb, const float* __restrict__ fw,
   const float* __restrict__ l1w, const float* __restrict__ l1b,
   const float* __restrict__ l2w, const float* __restrict__ l2b,
   const float* __restrict__ gkw) {
    int n = blockIdx.x;          // cout
    int c = threadIdx.x;         // cin = k
    __shared__ float ts[64], hs[256];
    __shared__ float sw_[64], swg[64];

    if (c < 64) ts[c] = g_t[c];
    __syncthreads();
    for (int u = c; u < 256; u += 192) {
        int b = u >> 6, j = u & 63;
        float a = l1b[j];
#pragma unroll
        for (int s = 0; s < 16; s++) a += ts[b * 16 + s] * l1w[j * 16 + s];
        hs[u] = 0.5f * a * (1.f + erff(a * 0.70710678118654752f));
    }
    __syncthreads();
    if (c < 64) {
        int b = c >> 4, s = c & 15;
        float a = l2b[s];
#pragma unroll
        for (int j = 0; j < 64; j++) a += hs[b * 64 + j] * l2w[s * 64 + j];
        float wv = 1.f / (1.f + expf(-a));
        sw_[c] = wv;
        swg[c] = wv * gkw[s];
    }
    __syncthreads();

    float f[17];
    const float* fp = fw + (size_t)n * ((WNN + 1) * CC) + c;
#pragma unroll
    for (int s = 0; s < 17; s++) f[s] = fp[s * CC];
    float g0 = gkb[0];

    int cg  = c >> 5, k32 = c & 31;
    int wrd = ((n >> 3) * 4 + (k32 >> 3)) * 64 + (n & 7) * 8 +
              (k32 & 3) * 2 + ((k32 >> 2) & 1);

#pragma unroll 1
    for (int tap = 0; tap < 9; tap++) {
        float kv[16];
        const float* kt = g_k1T + (size_t)tap * WNN * CC + c;
#pragma unroll
        for (int s = 0; s < 16; s++) kv[s] = kt[s * CC];
#pragma unroll
        for (int b = 0; b < 4; b++) {
            float acc = 0.f, ga = g0;
#pragma unroll
            for (int s = 0; s < 16; s++) {
                acc = fmaf(sw_[b * 16 + s] * kv[s], f[s], acc);
                ga  = fmaf(swg[b * 16 + s], kv[s], ga);
            }
            acc = fmaf(ga, f[16], acc);
            g_WeffB[((size_t)(b * 9 + tap) * 6 + cg) * 6144 + wrd] =
                __uint_as_float(f2tf(acc));
        }
    }
}

// ---------------------------------------------------------------------------
// Kernel D: tf32 mma.sync implicit GEMM.
// CTA: M=32 pixels x N=192, 8 warps, warp = 32m x 24n (acc 24/thread).
// Grid 512 -> 2 CTAs/SM -> 4 warps/SMSP for latency hiding.
// A/B fragment-ordered gmem -> registers; A shared 8-way via L1; B private
// per warp, double-buffered. No smem, no barriers.
// ---------------------------------------------------------------------------
__global__ void __launch_bounds__(256, 2)
kD(const float* __restrict__ fb, float* __restrict__ out) {
    int tid  = threadIdx.x;
    int lane = tid & 31;
    int wid  = tid >> 5;
    int b    = blockIdx.y;
    int mt   = blockIdx.x;             // 0..127: row = mt>>1, half = mt&1
    int row  = mt >> 1;
    int half = mt & 1;

    const float* WB = g_WeffB + (size_t)b * TAPS * 6 * 6144;
    int wn3 = wid * 3;                 // first n8-tile of this warp

    float acc[2][3][4];
#pragma unroll
    for (int mi = 0; mi < 2; mi++)
#pragma unroll
        for (int ni = 0; ni < 3; ni++)
#pragma unroll
            for (int r = 0; r < 4; r++) acc[mi][ni][r] = 0.f;

    uint32_t bfA[3][4][2], bfB[3][4][2];

    auto loadB = [&](int kc, uint32_t (&bf)[3][4][2]) {
        int tap = kc / 6, cg = kc - tap * 6;
        const float* src = WB + ((size_t)tap * 6 + cg) * 6144;
#pragma unroll
        for (int ni = 0; ni < 3; ni++)
#pragma unroll
            for (int ks = 0; ks < 4; ks++) {
                float2 v = *(const float2*)(src + ((wn3 + ni) * 4 + ks) * 64 + lane * 2);
                bf[ni][ks][0] = __float_as_uint(v.x);
                bf[ni][ks][1] = __float_as_uint(v.y);
            }
    };
    auto computeChunk = [&](int kc, uint32_t (&bf)[3][4][2]) {
        int tap = kc / 6, cg = kc - tap * 6;
        int dy = tap / 3 - 1, dxi = tap % 3;
        int sy = row + dy;
        if ((unsigned)sy >= RR) return;          // zero A -> no contribution
        const float* base = g_xA +
            ((((size_t)b * 3 + dxi) * RR + sy) * 6 + cg) * 2048;
#pragma unroll
        for (int ks = 0; ks < 4; ks++) {
            uint32_t af[2][4];
#pragma unroll
            for (int mi = 0; mi < 2; mi++) {
                float4 v = *(const float4*)(base +
                    (ks * 4 + half * 2 + mi) * 128 + lane * 4);
                af[mi][0] = __float_as_uint(v.x);
                af[mi][1] = __float_as_uint(v.y);
                af[mi][2] = __float_as_uint(v.z);
                af[mi][3] = __float_as_uint(v.w);
            }
#pragma unroll
            for (int mi = 0; mi < 2; mi++)
#pragma unroll
                for (int ni = 0; ni < 3; ni++)
                    mma_tf32(acc[mi][ni], af[mi], bf[ni][ks]);
        }
    };

    loadB(0, bfA);
#pragma unroll 1
    for (int it = 0; it < 27; it++) {
        int kc = it * 2;
        loadB(kc + 1, bfB);
        computeChunk(kc, bfA);
        if (kc + 2 < 54) loadB(kc + 2, bfA);
        computeChunk(kc + 1, bfB);
    }

    // ---- epilogue: +bias, STG.64 ----
#pragma unroll
    for (int ni = 0; ni < 3; ni++) {
        int co = wid * 24 + ni * 8 + (lane & 3) * 2;
        float bx = fb[co], by = fb[co + 1];
#pragma unroll
        for (int mi = 0; mi < 2; mi++) {
            int m0 = row * 64 + half * 32 + mi * 16 + (lane >> 2);
            size_t o0 = ((size_t)b * RR * RR + m0) * CC + co;
            *(float2*)(out + o0) =
                make_float2(acc[mi][ni][0] + bx, acc[mi][ni][1] + by);
            *(float2*)(out + o0 + (size_t)8 * CC) =
                make_float2(acc[mi][ni][2] + bx, acc[mi][ni][3] + by);
        }
    }
}

// ---------------------------------------------------------------------------
extern "C" void kernel_launch(void* const* d_in, const int* in_sizes, int n_in,
                              void* d_out, int out_size) {
    const float* x   = (const float*)d_in[0];
    const float* k1  = (const float*)d_in[1];
    const float* dcw = (const float*)d_in[2];
    const float* dcb = (const float*)d_in[3];
    const float* l1w = (const float*)d_in[4];
    const float* l1b = (const float*)d_in[5];
    const float* l2w = (const float*)d_in[6];
    const float* l2b = (const float*)d_in[7];
    const float* gkw = (const float*)d_in[8];
    const float* gkb = (const float*)d_in[9];
    const float* fw  = (const float*)d_in[10];
    const float* fb  = (const float*)d_in[11];
    float* out = (float*)d_out;

    static cudaStream_t s1 = nullptr;
    static cudaEvent_t evF = nullptr, evJ = nullptr;
    if (s1 == nullptr) {
        cudaStreamCreateWithFlags(&s1, cudaStreamNonBlocking);
        cudaEventCreateWithFlags(&evF, cudaEventDisableTiming);
        cudaEventCreateWithFlags(&evJ, cudaEventDisableTiming);
    }

    // fork: side chain (kT -> kA -> kW) runs concurrently with kX
    cudaEventRecord(evF, 0);
    cudaStreamWaitEvent(s1, evF, 0);

    kT<<<(TAPS * WNN * CC + 255) / 256, 256, 0, s1>>>(k1);
    kA<<<BB * WNN, CC, 0, s1>>>(x, k1, dcw, dcb);
    kW<<<CC, CC, 0, s1>>>(gkb, fw, l1w, l1b, l2w, l2b, gkw);
    cudaEventRecord(evJ, s1);

    kX<<<dim3(RR, 3, BB), 256>>>(x);

    // join
    cudaStreamWaitEvent(0, evJ, 0);
    dim3 g(2 * RR, BB);   // 128 half-row tiles x 4 batches = 512 CTAs
    kD<<<g, 256>>>(fb, out);
}